// round 16
// baseline (speedup 1.0000x reference)
#include <cuda_runtime.h>
#include <cstdint>

// Fixed problem shape: N=320000, C=64, B=4, NY=496, NX=432, NZ=1
#define NY_   496
#define NX_   432
#define C_    64
#define B_    4
#define NCELL (B_ * NY_ * NX_)        // 857,088 cells
#define NYNX  (NY_ * NX_)

#define RPB    2                      // y-rows per block
#define CELLS  (RPB * NX_)            // 864 cells per block
#define CCH    4                      // channels per chunk (16 chunks)
#define PITCH  868                    // floats per channel row in SMEM
#define THREADS_G 512
#define CH_BYTES (CELLS * 4)          // 3456 B per channel per block

// Winner encoding: 0 = empty, w = point_index + 1.
// __device__ globals are zero-initialized at module load; each gather block
// re-zeroes its own winner segment after consuming it, so the array is
// all-zero at every kernel_launch entry (identical state -> deterministic).
__device__ int4 g_winner4[NCELL / 4];

__device__ __forceinline__ uint32_t smem_u32(const void* p) {
    return (uint32_t)__cvta_generic_to_shared(p);
}

// ---------------------------------------------------------------------------
// Kernel 1: atomicMax scatter of (point index + 1). Last-write-wins == max.
// coors rows: (b, z, y, x), z == 0 always (NZ=1).
// ---------------------------------------------------------------------------
__global__ void scatter_winner_kernel(const int* __restrict__ coors, int n) {
    int i = blockIdx.x * blockDim.x + threadIdx.x;
    if (i < n) {
        int4 cz = *reinterpret_cast<const int4*>(coors + 4 * i);
        int cell = (cz.x * NY_ + cz.z) * NX_ + cz.w;
        atomicMax(reinterpret_cast<int*>(g_winner4) + cell, i + 1);
    }
}

// ---------------------------------------------------------------------------
// Kernel 2: gather + transpose with TMA bulk-copy stores.
// One block = 864 contiguous cells (b, y-pair) x 64 channels, 16 chunks of 4
// channels, double-buffered. Warps only do: LDG feature f4 -> 8 STS. The
// entire 219 MB output stream is written by cp.async.bulk (SMEM->GMEM, 3456 B
// contiguous per channel), overlapping the next chunk's gathers.
// Static SMEM: 2*4*868*4 + 864*4 = 31,232 B -> 4 blocks/SM (thread-capped).
// ---------------------------------------------------------------------------
__global__ __launch_bounds__(THREADS_G) void gather_pair_tma_kernel(
    const float* __restrict__ feat, float* __restrict__ out) {

    __shared__ int   sw[CELLS];                  // 3.4 KB
    __shared__ float tile[2][CCH * PITCH];       // 27.8 KB (2 buffers)

    int t = threadIdx.x;
    int p = blockIdx.x;                          // 0 .. 991
    int cell0 = p * CELLS;

    // Phase 0: winners -> SMEM (216 int4), then zero them for next replay.
    if (t < CELLS / 4) {
        int4 w4 = g_winner4[cell0 / 4 + t];
        *reinterpret_cast<int4*>(sw + 4 * t) = w4;
        g_winner4[cell0 / 4 + t] = make_int4(0, 0, 0, 0);
    }
    __syncthreads();

    int b  = p / (NY_ / RPB);
    int y0 = (p % (NY_ / RPB)) * RPB;
    size_t rowbase = ((size_t)(b * C_) * NY_ + y0) * NX_;

    bool hasB = (t + THREADS_G) < CELLS;         // t < 352
    const float4* srcA = nullptr;
    const float4* srcB = nullptr;
    {
        int wA = sw[t];
        if (wA > 0) srcA = reinterpret_cast<const float4*>(feat + (size_t)(wA - 1) * C_);
        if (hasB) {
            int wB = sw[t + THREADS_G];
            if (wB > 0) srcB = reinterpret_cast<const float4*>(feat + (size_t)(wB - 1) * C_);
        }
    }
    const float4 z4 = make_float4(0.f, 0.f, 0.f, 0.f);

    // Prefetch chunk 0: channels [0,4) = float4 index 0 of each row.
    float4 a = z4, bb = z4;
    if (srcA) a  = srcA[0];
    if (srcB) bb = srcB[0];

    #pragma unroll 4
    for (int ci = 0; ci < C_ / CCH; ci++) {      // 16 chunks
        int sel = ci & 1;

        // Recycle: ensure the bulk-group issued 2 iterations ago (same
        // buffer) has finished READING smem before we overwrite it.
        if (ci >= 2 && t == 0) {
            asm volatile("cp.async.bulk.wait_group.read 1;" ::: "memory");
        }
        __syncthreads();

        // Phase 2: transpose this chunk's 4 channels into the buffer.
        {
            float* tb = tile[sel];
            tb[0 * PITCH + t] = a.x;
            tb[1 * PITCH + t] = a.y;
            tb[2 * PITCH + t] = a.z;
            tb[3 * PITCH + t] = a.w;
            if (hasB) {
                int j = t + THREADS_G;
                tb[0 * PITCH + j] = bb.x;
                tb[1 * PITCH + j] = bb.y;
                tb[2 * PITCH + j] = bb.z;
                tb[3 * PITCH + j] = bb.w;
            }
        }
        __syncthreads();
        asm volatile("fence.proxy.async.shared::cta;" ::: "memory");

        // Issue 4 bulk copies (one per channel) + commit. Single thread.
        if (t == 0) {
            int cc = ci * CCH;
            #pragma unroll
            for (int k = 0; k < CCH; k++) {
                const float* g = out + rowbase + (size_t)(cc + k) * NYNX;
                uint32_t s = smem_u32(&tile[sel][k * PITCH]);
                asm volatile(
                    "cp.async.bulk.global.shared::cta.bulk_group [%0], [%1], %2;"
                    :: "l"(g), "r"(s), "n"(CH_BYTES) : "memory");
            }
            asm volatile("cp.async.bulk.commit_group;" ::: "memory");
        }

        // Prefetch next chunk's registers; LDGs fly during the next
        // wait_group + syncthreads.
        if (ci + 1 < C_ / CCH) {
            a = z4; bb = z4;
            if (srcA) a  = srcA[ci + 1];
            if (srcB) bb = srcB[ci + 1];
        }
    }

    // Drain all outstanding bulk stores before exit.
    if (t == 0) {
        asm volatile("cp.async.bulk.wait_group.read 0;" ::: "memory");
    }
}

// ---------------------------------------------------------------------------
extern "C" void kernel_launch(void* const* d_in, const int* in_sizes, int n_in,
                              void* d_out, int out_size) {
    const float* feat  = (const float*)d_in[0];   // [N, 64] float32
    const int*   coors = (const int*)d_in[1];     // [N, 4] int32
    (void)n_in; (void)out_size;

    int n = in_sizes[1] / 4;

    {   // 1) atomicMax (point index + 1); winner array is all-zero on entry
        int threads = 256;
        int blocks  = (n + threads - 1) / threads;
        scatter_winner_kernel<<<blocks, threads>>>(coors, n);
    }
    {   // 2) pair gather + transpose, TMA bulk stores (+ winner reset)
        int blocks = B_ * NY_ / RPB;   // 992
        gather_pair_tma_kernel<<<blocks, THREADS_G>>>(feat, (float*)d_out);
    }
}

// round 17
// speedup vs baseline: 1.0558x; 1.0558x over previous
#include <cuda_runtime.h>
#include <cstdint>

// Fixed problem shape: N=320000, C=64, B=4, NY=496, NX=432, NZ=1
#define NY_   496
#define NX_   432
#define C_    64
#define B_    4
#define NCELL (B_ * NY_ * NX_)        // 857,088 cells
#define NYNX  (NY_ * NX_)

#define RPB    2                      // y-rows per block
#define CELLS  (RPB * NX_)            // 864 cells per block
#define CCH    4                      // channels per chunk (16 chunks); 1 f4
#define NCHUNK (C_ / CCH)             // 16
#define PITCH  868                    // floats per channel row in SMEM
#define THREADS_G 512
#define CH_BYTES (CELLS * 4)          // 3456 B per channel per block

// Winner encoding: 0 = empty, w = point_index + 1.
// __device__ globals are zero-initialized at module load; each gather block
// re-zeroes its own winner segment after consuming it, so the array is
// all-zero at every kernel_launch entry (identical state -> deterministic).
__device__ int4 g_winner4[NCELL / 4];

__device__ __forceinline__ uint32_t smem_u32(const void* p) {
    return (uint32_t)__cvta_generic_to_shared(p);
}

// ---------------------------------------------------------------------------
// Kernel 1: atomicMax scatter of (point index + 1). Last-write-wins == max.
// coors rows: (b, z, y, x), z == 0 always (NZ=1).
// ---------------------------------------------------------------------------
__global__ void scatter_winner_kernel(const int* __restrict__ coors, int n) {
    int i = blockIdx.x * blockDim.x + threadIdx.x;
    if (i < n) {
        int4 cz = *reinterpret_cast<const int4*>(coors + 4 * i);
        int cell = (cz.x * NY_ + cz.z) * NX_ + cz.w;
        atomicMax(reinterpret_cast<int*>(g_winner4) + cell, i + 1);
    }
}

// ---------------------------------------------------------------------------
// Kernel 2: gather + transpose, TMA bulk stores, 2-LANE COOPERATIVE READS.
// Lane pair (2i, 2i+1) loads the two f4s of one 32 B feature sector in the
// SAME warp instruction -> L1 wavefronts per read halve vs thread=cell.
// Even lane holds chunk cb, odd lane holds chunk cb+1; STS alternates halves.
// Double-buffered CCH=4 tile; cp.async.bulk writes 3456 B per channel.
// Static SMEM: 2*4*868*4 + 864*4 = 31,232 B.
// ---------------------------------------------------------------------------
__global__ __launch_bounds__(THREADS_G, 4) void gather_pair_coop_kernel(
    const float* __restrict__ feat, float* __restrict__ out) {

    __shared__ int   sw[CELLS];                  // 3.4 KB
    __shared__ float tile[2][CCH * PITCH];       // 27.8 KB

    int t = threadIdx.x;
    int p = blockIdx.x;                          // 0 .. 991
    int cell0 = p * CELLS;
    int pairid = t >> 1;                         // 0..255
    int half   = t & 1;                          // f4 parity within 32 B

    // Phase 0: winners -> SMEM (216 int4), then zero them for next replay.
    if (t < CELLS / 4) {
        int4 w4 = g_winner4[cell0 / 4 + t];
        *reinterpret_cast<int4*>(sw + 4 * t) = w4;
        g_winner4[cell0 / 4 + t] = make_int4(0, 0, 0, 0);
    }
    __syncthreads();

    int b  = p / (NY_ / RPB);
    int y0 = (p % (NY_ / RPB)) * RPB;
    size_t rowbase = ((size_t)(b * C_) * NY_ + y0) * NX_;

    const float4 z4 = make_float4(0.f, 0.f, 0.f, 0.f);
    float4 v0, v1, v2, v3;   // owned cells: pairid + {0,256,512,768}

    // Load event: both lanes of a pair fetch f4 (cb + half) of each owned
    // cell's row -- one 32 B sector per pair per cell, shared L1 line.
    auto load_pair = [&](int cb) {
        int f4i = cb + half;
        v0 = z4; v1 = z4; v2 = z4; v3 = z4;
        {
            int w = sw[pairid];
            if (w > 0) v0 = reinterpret_cast<const float4*>(feat + (size_t)(w - 1) * C_)[f4i];
        }
        {
            int w = sw[pairid + 256];
            if (w > 0) v1 = reinterpret_cast<const float4*>(feat + (size_t)(w - 1) * C_)[f4i];
        }
        {
            int w = sw[pairid + 512];
            if (w > 0) v2 = reinterpret_cast<const float4*>(feat + (size_t)(w - 1) * C_)[f4i];
        }
        if (pairid < 96) {
            int w = sw[pairid + 768];
            if (w > 0) v3 = reinterpret_cast<const float4*>(feat + (size_t)(w - 1) * C_)[f4i];
        }
    };

    load_pair(0);   // chunks 0 (even lanes) and 1 (odd lanes)

    #pragma unroll 4
    for (int ci = 0; ci < NCHUNK; ci++) {        // 16 chunks
        int sel = ci & 1;

        // Recycle: bulk-group issued 2 iterations ago must be done reading.
        if (ci >= 2 && t == 0) {
            asm volatile("cp.async.bulk.wait_group.read 1;" ::: "memory");
        }
        __syncthreads();

        // Phase 2: lanes whose half matches this chunk write their cells.
        if (half == (ci & 1)) {
            float* tb = tile[sel];
            int j = pairid;
            tb[0 * PITCH + j] = v0.x; tb[1 * PITCH + j] = v0.y;
            tb[2 * PITCH + j] = v0.z; tb[3 * PITCH + j] = v0.w;
            j = pairid + 256;
            tb[0 * PITCH + j] = v1.x; tb[1 * PITCH + j] = v1.y;
            tb[2 * PITCH + j] = v1.z; tb[3 * PITCH + j] = v1.w;
            j = pairid + 512;
            tb[0 * PITCH + j] = v2.x; tb[1 * PITCH + j] = v2.y;
            tb[2 * PITCH + j] = v2.z; tb[3 * PITCH + j] = v2.w;
            if (pairid < 96) {
                j = pairid + 768;
                tb[0 * PITCH + j] = v3.x; tb[1 * PITCH + j] = v3.y;
                tb[2 * PITCH + j] = v3.z; tb[3 * PITCH + j] = v3.w;
            }
        }

        // After the odd half stores, all v dead -> load next chunk pair.
        if ((ci & 1) == 1 && ci + 1 < NCHUNK) {
            load_pair(ci + 1);
        }

        __syncthreads();
        asm volatile("fence.proxy.async.shared::cta;" ::: "memory");

        // Issue 4 bulk copies (one per channel) + commit. Single thread.
        if (t == 0) {
            int cc = ci * CCH;
            #pragma unroll
            for (int k = 0; k < CCH; k++) {
                const float* g = out + rowbase + (size_t)(cc + k) * NYNX;
                uint32_t s = smem_u32(&tile[sel][k * PITCH]);
                asm volatile(
                    "cp.async.bulk.global.shared::cta.bulk_group [%0], [%1], %2;"
                    :: "l"(g), "r"(s), "n"(CH_BYTES) : "memory");
            }
            asm volatile("cp.async.bulk.commit_group;" ::: "memory");
        }
    }

    // Drain all outstanding bulk stores before exit.
    if (t == 0) {
        asm volatile("cp.async.bulk.wait_group.read 0;" ::: "memory");
    }
}

// ---------------------------------------------------------------------------
extern "C" void kernel_launch(void* const* d_in, const int* in_sizes, int n_in,
                              void* d_out, int out_size) {
    const float* feat  = (const float*)d_in[0];   // [N, 64] float32
    const int*   coors = (const int*)d_in[1];     // [N, 4] int32
    (void)n_in; (void)out_size;

    int n = in_sizes[1] / 4;

    {   // 1) atomicMax (point index + 1); winner array is all-zero on entry
        int threads = 256;
        int blocks  = (n + threads - 1) / threads;
        scatter_winner_kernel<<<blocks, threads>>>(coors, n);
    }
    {   // 2) coop-read gather + transpose, TMA bulk stores (+ winner reset)
        int blocks = B_ * NY_ / RPB;   // 992
        gather_pair_coop_kernel<<<blocks, THREADS_G>>>(feat, (float*)d_out);
    }
}